// round 16
// baseline (speedup 1.0000x reference)
#include <cuda_runtime.h>
#include <cstdint>
#include <math.h>

#define HH 256
#define WW 256
#define NPIX 65536
#define CCH 32

// ---------------- scratch ----------------
__device__ float g_D[2 * NPIX];        // reference-ordered patch SSD table
__device__ float4 g_N4[5 * 4 * NPIX];  // normals: idx = it*262144 + gtid, (s0,s1,s2,s3)

struct AllKeys { uint32_t k[5][4][2]; };

// ---------------- threefry-2x32 ----------------
__host__ __device__ __forceinline__ uint32_t rotl32(uint32_t v, int d) {
#ifdef __CUDA_ARCH__
    return __funnelshift_l(v, v, d);
#else
    return (v << d) | (v >> (32 - d));
#endif
}

__host__ __device__ __forceinline__ void threefry(uint32_t k0, uint32_t k1,
                                                  uint32_t x0, uint32_t x1,
                                                  uint32_t& o0, uint32_t& o1) {
    uint32_t k2 = k0 ^ k1 ^ 0x1BD11BDAu;
    x0 += k0; x1 += k1;
    x0 += x1; x1 = rotl32(x1, 13); x1 ^= x0;
    x0 += x1; x1 = rotl32(x1, 15); x1 ^= x0;
    x0 += x1; x1 = rotl32(x1, 26); x1 ^= x0;
    x0 += x1; x1 = rotl32(x1, 6);  x1 ^= x0;
    x0 += k1; x1 += k2 + 1u;
    x0 += x1; x1 = rotl32(x1, 17); x1 ^= x0;
    x0 += x1; x1 = rotl32(x1, 29); x1 ^= x0;
    x0 += x1; x1 = rotl32(x1, 16); x1 ^= x0;
    x0 += x1; x1 = rotl32(x1, 24); x1 ^= x0;
    x0 += k2; x1 += k0 + 2u;
    x0 += x1; x1 = rotl32(x1, 13); x1 ^= x0;
    x0 += x1; x1 = rotl32(x1, 15); x1 ^= x0;
    x0 += x1; x1 = rotl32(x1, 26); x1 ^= x0;
    x0 += x1; x1 = rotl32(x1, 6);  x1 ^= x0;
    x0 += k0; x1 += k1 + 3u;
    x0 += x1; x1 = rotl32(x1, 17); x1 ^= x0;
    x0 += x1; x1 = rotl32(x1, 29); x1 ^= x0;
    x0 += x1; x1 = rotl32(x1, 16); x1 ^= x0;
    x0 += x1; x1 = rotl32(x1, 24); x1 ^= x0;
    x0 += k1; x1 += k2 + 4u;
    x0 += x1; x1 = rotl32(x1, 13); x1 ^= x0;
    x0 += x1; x1 = rotl32(x1, 15); x1 ^= x0;
    x0 += x1; x1 = rotl32(x1, 26); x1 ^= x0;
    x0 += x1; x1 = rotl32(x1, 6);  x1 ^= x0;
    x0 += k2; x1 += k0 + 5u;
    o0 = x0; o1 = x1;
}

__device__ __forceinline__ uint32_t rnd32(uint32_t k0, uint32_t k1, uint32_t i) {
    uint32_t o0, o1;
    threefry(k0, k1, 0u, i, o0, o1);
    return o0 ^ o1;
}

// ---------------- float helpers (XLA-matching: NO fma contraction) ----------------
__device__ __forceinline__ float bits_to_f01(uint32_t v) {
    return __fadd_rn(__uint_as_float((v >> 9) | 0x3F800000u), -1.0f);
}

__device__ __forceinline__ float erfinv_xla(float x) {
    float t = __fmul_rn(x, x);
    float w = -log1pf(-t);
    float p;
    if (w < 5.0f) {
        w = __fadd_rn(w, -2.5f);
        p = 2.81022636e-08f;
        p = __fadd_rn(3.43273939e-07f,  __fmul_rn(p, w));
        p = __fadd_rn(-3.5233877e-06f,  __fmul_rn(p, w));
        p = __fadd_rn(-4.39150654e-06f, __fmul_rn(p, w));
        p = __fadd_rn(0.00021858087f,   __fmul_rn(p, w));
        p = __fadd_rn(-0.00125372503f,  __fmul_rn(p, w));
        p = __fadd_rn(-0.00417768164f,  __fmul_rn(p, w));
        p = __fadd_rn(0.246640727f,     __fmul_rn(p, w));
        p = __fadd_rn(1.50140941f,      __fmul_rn(p, w));
    } else {
        w = __fadd_rn(__fsqrt_rn(w), -3.0f);
        p = -0.000200214257f;
        p = __fadd_rn(0.000100950558f,  __fmul_rn(p, w));
        p = __fadd_rn(0.00134934322f,   __fmul_rn(p, w));
        p = __fadd_rn(-0.00367342844f,  __fmul_rn(p, w));
        p = __fadd_rn(0.00573950773f,   __fmul_rn(p, w));
        p = __fadd_rn(-0.0076224613f,   __fmul_rn(p, w));
        p = __fadd_rn(0.00943887047f,   __fmul_rn(p, w));
        p = __fadd_rn(1.00167406f,      __fmul_rn(p, w));
        p = __fadd_rn(2.83297682f,      __fmul_rn(p, w));
    }
    return __fmul_rn(p, x);
}

__device__ __forceinline__ float normal_from_bits(uint32_t v) {
    float f = bits_to_f01(v);
    float u = __fadd_rn(__fmul_rn(f, 2.0f), -0.99999994f);
    u = fmaxf(-0.99999994f, u);
    return __fmul_rn(1.4142135623730951f, erfinv_xla(u));
}

__device__ __forceinline__ float clipc(float v) {
    return fminf(fmaxf(v, 0.0f), 255.0f);
}

__device__ __forceinline__ int daddr(int b, float y, float x) {
    int iy = __float2int_rn(y);
    int ix = __float2int_rn(x);
    iy = min(max(iy, 0), HH - 1);
    ix = min(max(ix, 0), WW - 1);
    return b * NPIX + iy * WW + ix;
}

// ---------------- kernel 1: heterogeneous prep (RNG blocks FIRST) ----------------
// blocks [0, 1024):    normal table fill (20 threefry+erfinv, 5 float4 stores)
// blocks [1024, 2048): fused SQ + strict-order D via 16x8 smem halo tiles (23 KB)
#define TSX 16
#define TSY 8
#define HX 18
#define HY 10
#define HSLOTS (HX * HY)   // 180

__global__ __launch_bounds__(256, 6) void kPrep(const float* __restrict__ src,
                                                const float* __restrict__ tgt,
                                                AllKeys keys) {
    __shared__ float sq[CCH * HSLOTS];   // 23040 B -> 6 blocks/SM
    int tid = threadIdx.x;
    int bi  = blockIdx.x;

    if (bi >= 1024) {
        // ---- SQ + D tile (16x8) ----
        int tb = bi - 1024;
        int tileX = tb & 15;            // 16 tiles across
        int tileY = (tb >> 4) & 31;     // 32 tile-rows
        int b     = tb >> 9;
        int baseY = tileY * TSY - 1;
        int baseX = tileX * TSX - 1;

        if (tid < HSLOTS) {
            int yh = tid / HX, xh = tid % HX;
            int gy = baseY + yh, gx = baseX + xh;
            bool inb = ((unsigned)gy < HH) && ((unsigned)gx < WW);
            int gidx = (b * CCH) * NPIX + gy * WW + gx;
#pragma unroll
            for (int c = 0; c < CCH; c++) {
                float v = 0.0f;
                if (inb) {
                    float d = __fsub_rn(__ldg(&src[gidx + c * NPIX]),
                                        __ldg(&tgt[gidx + c * NPIX]));
                    v = __fmul_rn(d, d);
                }
                sq[c * HSLOTS + tid] = v;
            }
        }
        __syncthreads();

        if (tid < TSX * TSY) {
            int tx = tid & 15, ty = tid >> 4;
            float acc = 0.0f;
#pragma unroll
            for (int dy = 0; dy < 3; dy++) {
#pragma unroll
                for (int dx = 0; dx < 3; dx++) {
                    const float* pb = &sq[(ty + dy) * HX + (tx + dx)];
#pragma unroll
                    for (int c = 0; c < CCH; c++) {
                        acc = __fadd_rn(acc, pb[c * HSLOTS]);
                    }
                }
            }
            g_D[b * NPIX + (tileY * TSY + ty) * WW + (tileX * TSX + tx)] = acc;
        }
    } else {
        // ---- normal table: thread <-> counter gtid; float4 (s0..s3) per iter ----
        uint32_t gtid = (uint32_t)(bi * 256 + tid);   // 0..262143
#pragma unroll
        for (int it = 0; it < 5; it++) {
            float n0 = normal_from_bits(rnd32(keys.k[it][0][0], keys.k[it][0][1], gtid));
            float n1 = normal_from_bits(rnd32(keys.k[it][1][0], keys.k[it][1][1], gtid));
            float n2 = normal_from_bits(rnd32(keys.k[it][2][0], keys.k[it][2][1], gtid));
            float n3 = normal_from_bits(rnd32(keys.k[it][3][0], keys.k[it][3][1], gtid));
            g_N4[(uint32_t)it * 262144u + gtid] = make_float4(n0, n1, n2, n3);
        }
    }
}

// ---------------- kernel 2: init + 5 iterations, halo-split rows ----------------
// Full 4-step speculative random search: all 15 candidate positions (binary
// outcome tree) computed up-front, ONE parallel 15-load D wall per iteration,
// then nested-select resolution — bit-identical to the sequential chain.
#define WIN 138
#define OWN 128
#define HALO 5
#define MTHREADS 160

__global__ __launch_bounds__(MTHREADS) void kMatch(float* __restrict__ out,
                                                   uint32_t ka, uint32_t kb) {
    __shared__ float sy[2][WIN + 2], sx[2][WIN + 2], sd[2][WIN + 2];
    int bi  = blockIdx.x;                 // 0..1023
    int b   = bi >> 9;                    // batch
    int rem = bi & 511;
    int row = rem >> 1;
    int seg = rem & 1;
    int base = seg * OWN;
    int wp  = threadIdx.x;                // 0..159; active if < WIN
    bool act = wp < WIN;

    int j = (base + wp - HALO) & 255;     // circular column
    int p = (row << 8) | j;

    uint32_t ciy = (uint32_t)(b * 131072 + p);
    uint32_t cix = ciy + 65536u;

    float y = 0.0f, x = 0.0f, d = 0.0f;
    float4 ny4 = make_float4(0.f, 0.f, 0.f, 0.f), nx4 = ny4;
    if (act) {
        y = __fmul_rn(bits_to_f01(rnd32(ka, kb, ciy)), 255.0f);
        x = __fmul_rn(bits_to_f01(rnd32(ka, kb, cix)), 255.0f);
        d = __ldg(&g_D[daddr(b, y, x)]);
        ny4 = __ldg(&g_N4[ciy]);          // iteration 0 normals
        nx4 = __ldg(&g_N4[cix]);
    }

    int tm = max(wp - 1, 0);              // clamped: edges are eroded anyway
    int tp = min(wp + 1, WIN - 1);

#pragma unroll
    for (int it = 0; it < 5; it++) {
        int cb = it & 1;
        if (act) { sy[cb][wp] = y; sx[cb][wp] = x; sd[cb][wp] = d; }

        // prefetch next iteration's normals (hidden under sync + gather wall)
        float4 ny4n = make_float4(0.f, 0.f, 0.f, 0.f), nx4n = ny4n;
        if (act && it < 4) {
            uint32_t nb = (uint32_t)(it + 1) * 262144u;
            ny4n = __ldg(&g_N4[nb + ciy]);
            nx4n = __ldg(&g_N4[nb + cix]);
        }

        __syncthreads();
        float my = sy[cb][tm], mx = sx[cb][tm], md = sd[cb][tm];
        float qy = sy[cb][tp], qx = sx[cb][tp], qd = sd[cb][tp];
        // single sync per iteration: next iteration writes the other buffer

        if (act) {
            // propagate(+1) at j and j+1, then propagate(-1) at j
            float c0y, c0x, c0d, c1y, c1x, c1d;
            if (md < d) { c0y = my; c0x = mx; c0d = md; } else { c0y = y; c0x = x; c0d = d; }
            if (d < qd) { c1y = y;  c1x = x;  c1d = d;  } else { c1y = qy; c1x = qx; c1d = qd; }
            if (c1d < c0d) { y = c1y; x = c1x; d = c1d; } else { y = c0y; x = c0x; d = c0d; }

            // ---- full speculative 4-step tree: 15 positions, one load wall ----
            // step1 candidate
            float ay  = clipc(__fadd_rn(y, __fmul_rn(ny4.x, 1.0f)));
            float ax  = clipc(__fadd_rn(x, __fmul_rn(nx4.x, 1.0f)));
            // step2 candidates from {P0, a}
            float b0y = clipc(__fadd_rn(y,  __fmul_rn(ny4.y, 0.5f)));
            float b0x = clipc(__fadd_rn(x,  __fmul_rn(nx4.y, 0.5f)));
            float b1y = clipc(__fadd_rn(ay, __fmul_rn(ny4.y, 0.5f)));
            float b1x = clipc(__fadd_rn(ax, __fmul_rn(nx4.y, 0.5f)));
            // step3 candidates from states {P0, b0, a, b1}
            float e0y = clipc(__fadd_rn(y,   __fmul_rn(ny4.z, 0.25f)));
            float e0x = clipc(__fadd_rn(x,   __fmul_rn(nx4.z, 0.25f)));
            float e1y = clipc(__fadd_rn(b0y, __fmul_rn(ny4.z, 0.25f)));
            float e1x = clipc(__fadd_rn(b0x, __fmul_rn(nx4.z, 0.25f)));
            float e2y = clipc(__fadd_rn(ay,  __fmul_rn(ny4.z, 0.25f)));
            float e2x = clipc(__fadd_rn(ax,  __fmul_rn(nx4.z, 0.25f)));
            float e3y = clipc(__fadd_rn(b1y, __fmul_rn(ny4.z, 0.25f)));
            float e3x = clipc(__fadd_rn(b1x, __fmul_rn(nx4.z, 0.25f)));
            // step4 candidates from the 8 post-step3 states, outcome order
            // (acc1,acc2,acc3): P0,e0,b0,e1,a,e2,b1,e3
            float f0y = clipc(__fadd_rn(y,   __fmul_rn(ny4.w, 0.125f)));
            float f0x = clipc(__fadd_rn(x,   __fmul_rn(nx4.w, 0.125f)));
            float f1y = clipc(__fadd_rn(e0y, __fmul_rn(ny4.w, 0.125f)));
            float f1x = clipc(__fadd_rn(e0x, __fmul_rn(nx4.w, 0.125f)));
            float f2y = clipc(__fadd_rn(b0y, __fmul_rn(ny4.w, 0.125f)));
            float f2x = clipc(__fadd_rn(b0x, __fmul_rn(nx4.w, 0.125f)));
            float f3y = clipc(__fadd_rn(e1y, __fmul_rn(ny4.w, 0.125f)));
            float f3x = clipc(__fadd_rn(e1x, __fmul_rn(nx4.w, 0.125f)));
            float f4y = clipc(__fadd_rn(ay,  __fmul_rn(ny4.w, 0.125f)));
            float f4x = clipc(__fadd_rn(ax,  __fmul_rn(nx4.w, 0.125f)));
            float f5y = clipc(__fadd_rn(e2y, __fmul_rn(ny4.w, 0.125f)));
            float f5x = clipc(__fadd_rn(e2x, __fmul_rn(nx4.w, 0.125f)));
            float f6y = clipc(__fadd_rn(b1y, __fmul_rn(ny4.w, 0.125f)));
            float f6x = clipc(__fadd_rn(b1x, __fmul_rn(nx4.w, 0.125f)));
            float f7y = clipc(__fadd_rn(e3y, __fmul_rn(ny4.w, 0.125f)));
            float f7x = clipc(__fadd_rn(e3x, __fmul_rn(nx4.w, 0.125f)));

            // ONE parallel load wall (15 independent L2 hits)
            float da  = __ldg(&g_D[daddr(b, ay,  ax)]);
            float db0 = __ldg(&g_D[daddr(b, b0y, b0x)]);
            float db1 = __ldg(&g_D[daddr(b, b1y, b1x)]);
            float de0 = __ldg(&g_D[daddr(b, e0y, e0x)]);
            float de1 = __ldg(&g_D[daddr(b, e1y, e1x)]);
            float de2 = __ldg(&g_D[daddr(b, e2y, e2x)]);
            float de3 = __ldg(&g_D[daddr(b, e3y, e3x)]);
            float df0 = __ldg(&g_D[daddr(b, f0y, f0x)]);
            float df1 = __ldg(&g_D[daddr(b, f1y, f1x)]);
            float df2 = __ldg(&g_D[daddr(b, f2y, f2x)]);
            float df3 = __ldg(&g_D[daddr(b, f3y, f3x)]);
            float df4 = __ldg(&g_D[daddr(b, f4y, f4x)]);
            float df5 = __ldg(&g_D[daddr(b, f5y, f5x)]);
            float df6 = __ldg(&g_D[daddr(b, f6y, f6x)]);
            float df7 = __ldg(&g_D[daddr(b, f7y, f7x)]);

            // resolve step 1
            bool a1 = da < d;
            if (a1) { y = ay; x = ax; d = da; }
            // resolve step 2
            float dbv = a1 ? db1 : db0;
            float bvy = a1 ? b1y : b0y;
            float bvx = a1 ? b1x : b0x;
            bool a2 = dbv < d;
            if (a2) { y = bvy; x = bvx; d = dbv; }
            // resolve step 3
            float dev = a1 ? (a2 ? de3 : de2) : (a2 ? de1 : de0);
            float evy = a1 ? (a2 ? e3y : e2y) : (a2 ? e1y : e0y);
            float evx = a1 ? (a2 ? e3x : e2x) : (a2 ? e1x : e0x);
            bool a3 = dev < d;
            if (a3) { y = evy; x = evx; d = dev; }
            // resolve step 4
            float dfv = a1 ? (a2 ? (a3 ? df7 : df6) : (a3 ? df5 : df4))
                           : (a2 ? (a3 ? df3 : df2) : (a3 ? df1 : df0));
            float fvy = a1 ? (a2 ? (a3 ? f7y : f6y) : (a3 ? f5y : f4y))
                           : (a2 ? (a3 ? f3y : f2y) : (a3 ? f1y : f0y));
            float fvx = a1 ? (a2 ? (a3 ? f7x : f6x) : (a3 ? f5x : f4x))
                           : (a2 ? (a3 ? f3x : f2x) : (a3 ? f1x : f0x));
            if (dfv < d) { y = fvy; x = fvx; d = dfv; }
        }
        ny4 = ny4n; nx4 = nx4n;
    }

    if (wp >= HALO && wp < HALO + OWN) {
        out[b * 131072 + p]        = y;
        out[b * 131072 + NPIX + p] = x;
    }
}

// ---------------- host ----------------
extern "C" void kernel_launch(void* const* d_in, const int* in_sizes, int n_in,
                              void* d_out, int out_size) {
    const float* src = (const float*)d_in[0];
    const float* tgt = (const float*)d_in[1];
    float* out = (float*)d_out;
    (void)in_sizes; (void)n_in; (void)out_size;

    uint32_t ki0, ki1, kl0, kl1;
    threefry(0u, 1u, 0u, 0u, ki0, ki1);   // k_init
    threefry(0u, 1u, 0u, 1u, kl0, kl1);   // k_loop

    AllKeys keys;
    for (uint32_t t = 0; t < 5; t++) {
        uint32_t K0, K1;
        threefry(kl0, kl1, 0u, t, K0, K1);        // fold_in(k_loop, t)
        for (int s = 0; s < 4; s++) {
            uint32_t n0, n1, s0, s1;
            threefry(K0, K1, 0u, 0u, n0, n1);     // next key
            threefry(K0, K1, 0u, 1u, s0, s1);     // key for normal draw
            keys.k[t][s][0] = s0;
            keys.k[t][s][1] = s1;
            K0 = n0; K1 = n1;
        }
    }

    kPrep<<<2048, 256>>>(src, tgt, keys);
    kMatch<<<1024, MTHREADS>>>(out, ki0, ki1);
}

// round 17
// speedup vs baseline: 1.1976x; 1.1976x over previous
#include <cuda_runtime.h>
#include <cstdint>
#include <math.h>

#define HH 256
#define WW 256
#define NPIX 65536
#define CCH 32

// ---------------- scratch ----------------
__device__ float g_D[2 * NPIX];        // reference-ordered patch SSD table
__device__ float4 g_N4[5 * 4 * NPIX];  // normals: idx = it*262144 + gtid, (s0,s1,s2,s3)

struct AllKeys { uint32_t k[5][4][2]; };

// ---------------- threefry-2x32 ----------------
__host__ __device__ __forceinline__ uint32_t rotl32(uint32_t v, int d) {
#ifdef __CUDA_ARCH__
    return __funnelshift_l(v, v, d);
#else
    return (v << d) | (v >> (32 - d));
#endif
}

__host__ __device__ __forceinline__ void threefry(uint32_t k0, uint32_t k1,
                                                  uint32_t x0, uint32_t x1,
                                                  uint32_t& o0, uint32_t& o1) {
    uint32_t k2 = k0 ^ k1 ^ 0x1BD11BDAu;
    x0 += k0; x1 += k1;
    x0 += x1; x1 = rotl32(x1, 13); x1 ^= x0;
    x0 += x1; x1 = rotl32(x1, 15); x1 ^= x0;
    x0 += x1; x1 = rotl32(x1, 26); x1 ^= x0;
    x0 += x1; x1 = rotl32(x1, 6);  x1 ^= x0;
    x0 += k1; x1 += k2 + 1u;
    x0 += x1; x1 = rotl32(x1, 17); x1 ^= x0;
    x0 += x1; x1 = rotl32(x1, 29); x1 ^= x0;
    x0 += x1; x1 = rotl32(x1, 16); x1 ^= x0;
    x0 += x1; x1 = rotl32(x1, 24); x1 ^= x0;
    x0 += k2; x1 += k0 + 2u;
    x0 += x1; x1 = rotl32(x1, 13); x1 ^= x0;
    x0 += x1; x1 = rotl32(x1, 15); x1 ^= x0;
    x0 += x1; x1 = rotl32(x1, 26); x1 ^= x0;
    x0 += x1; x1 = rotl32(x1, 6);  x1 ^= x0;
    x0 += k0; x1 += k1 + 3u;
    x0 += x1; x1 = rotl32(x1, 17); x1 ^= x0;
    x0 += x1; x1 = rotl32(x1, 29); x1 ^= x0;
    x0 += x1; x1 = rotl32(x1, 16); x1 ^= x0;
    x0 += x1; x1 = rotl32(x1, 24); x1 ^= x0;
    x0 += k1; x1 += k2 + 4u;
    x0 += x1; x1 = rotl32(x1, 13); x1 ^= x0;
    x0 += x1; x1 = rotl32(x1, 15); x1 ^= x0;
    x0 += x1; x1 = rotl32(x1, 26); x1 ^= x0;
    x0 += x1; x1 = rotl32(x1, 6);  x1 ^= x0;
    x0 += k2; x1 += k0 + 5u;
    o0 = x0; o1 = x1;
}

__device__ __forceinline__ uint32_t rnd32(uint32_t k0, uint32_t k1, uint32_t i) {
    uint32_t o0, o1;
    threefry(k0, k1, 0u, i, o0, o1);
    return o0 ^ o1;
}

// ---------------- float helpers (XLA-matching: NO fma contraction) ----------------
__device__ __forceinline__ float bits_to_f01(uint32_t v) {
    return __fadd_rn(__uint_as_float((v >> 9) | 0x3F800000u), -1.0f);
}

__device__ __forceinline__ float erfinv_xla(float x) {
    float t = __fmul_rn(x, x);
    float w = -log1pf(-t);
    float p;
    if (w < 5.0f) {
        w = __fadd_rn(w, -2.5f);
        p = 2.81022636e-08f;
        p = __fadd_rn(3.43273939e-07f,  __fmul_rn(p, w));
        p = __fadd_rn(-3.5233877e-06f,  __fmul_rn(p, w));
        p = __fadd_rn(-4.39150654e-06f, __fmul_rn(p, w));
        p = __fadd_rn(0.00021858087f,   __fmul_rn(p, w));
        p = __fadd_rn(-0.00125372503f,  __fmul_rn(p, w));
        p = __fadd_rn(-0.00417768164f,  __fmul_rn(p, w));
        p = __fadd_rn(0.246640727f,     __fmul_rn(p, w));
        p = __fadd_rn(1.50140941f,      __fmul_rn(p, w));
    } else {
        w = __fadd_rn(__fsqrt_rn(w), -3.0f);
        p = -0.000200214257f;
        p = __fadd_rn(0.000100950558f,  __fmul_rn(p, w));
        p = __fadd_rn(0.00134934322f,   __fmul_rn(p, w));
        p = __fadd_rn(-0.00367342844f,  __fmul_rn(p, w));
        p = __fadd_rn(0.00573950773f,   __fmul_rn(p, w));
        p = __fadd_rn(-0.0076224613f,   __fmul_rn(p, w));
        p = __fadd_rn(0.00943887047f,   __fmul_rn(p, w));
        p = __fadd_rn(1.00167406f,      __fmul_rn(p, w));
        p = __fadd_rn(2.83297682f,      __fmul_rn(p, w));
    }
    return __fmul_rn(p, x);
}

__device__ __forceinline__ float normal_from_bits(uint32_t v) {
    float f = bits_to_f01(v);
    float u = __fadd_rn(__fmul_rn(f, 2.0f), -0.99999994f);
    u = fmaxf(-0.99999994f, u);
    return __fmul_rn(1.4142135623730951f, erfinv_xla(u));
}

__device__ __forceinline__ float clipc(float v) {
    return fminf(fmaxf(v, 0.0f), 255.0f);
}

__device__ __forceinline__ int daddr(int b, float y, float x) {
    int iy = __float2int_rn(y);
    int ix = __float2int_rn(x);
    iy = min(max(iy, 0), HH - 1);
    ix = min(max(ix, 0), WW - 1);
    return b * NPIX + iy * WW + ix;
}

// ---------------- kernel 1: heterogeneous prep (RNG blocks FIRST) ----------------
// blocks [0, 1024):    normal table fill (20 threefry+erfinv, 5 float4 stores)
// blocks [1024, 1536): fused SQ + strict-order D via 32x8 smem halo tiles
#define TSX 32
#define TSY 8
#define HX 34
#define HSLOTS (HX * 10)   // 340

__global__ __launch_bounds__(256, 4) void kPrep(const float* __restrict__ src,
                                                const float* __restrict__ tgt,
                                                AllKeys keys) {
    __shared__ float sq[CCH * HSLOTS];   // 43520 B
    int tid = threadIdx.x;
    int bi  = blockIdx.x;

    if (bi >= 1024) {
        // ---- SQ + D tile ----
        int tb = bi - 1024;
        int tileX = tb & 7;
        int tileY = (tb >> 3) & 31;
        int b     = tb >> 8;
        int baseY = tileY * TSY - 1;
        int baseX = tileX * TSX - 1;

        {
            int j = tid;
            int yh = j / HX, xh = j % HX;
            int gy = baseY + yh, gx = baseX + xh;
            bool inb = ((unsigned)gy < HH) && ((unsigned)gx < WW);
            int gidx = (b * CCH) * NPIX + gy * WW + gx;
#pragma unroll
            for (int c = 0; c < CCH; c++) {
                float v = 0.0f;
                if (inb) {
                    float d = __fsub_rn(__ldg(&src[gidx + c * NPIX]),
                                        __ldg(&tgt[gidx + c * NPIX]));
                    v = __fmul_rn(d, d);
                }
                sq[c * HSLOTS + j] = v;
            }
            int j2 = tid + 256;
            if (j2 < HSLOTS) {
                int yh2 = j2 / HX, xh2 = j2 % HX;
                int gy2 = baseY + yh2, gx2 = baseX + xh2;
                bool inb2 = ((unsigned)gy2 < HH) && ((unsigned)gx2 < WW);
                int gidx2 = (b * CCH) * NPIX + gy2 * WW + gx2;
#pragma unroll
                for (int c = 0; c < CCH; c++) {
                    float v = 0.0f;
                    if (inb2) {
                        float d = __fsub_rn(__ldg(&src[gidx2 + c * NPIX]),
                                            __ldg(&tgt[gidx2 + c * NPIX]));
                        v = __fmul_rn(d, d);
                    }
                    sq[c * HSLOTS + j2] = v;
                }
            }
        }
        __syncthreads();

        int tx = tid & 31, ty = tid >> 5;
        float acc = 0.0f;
#pragma unroll
        for (int dy = 0; dy < 3; dy++) {
#pragma unroll
            for (int dx = 0; dx < 3; dx++) {
                const float* pb = &sq[(ty + dy) * HX + (tx + dx)];
#pragma unroll
                for (int c = 0; c < CCH; c++) {
                    acc = __fadd_rn(acc, pb[c * HSLOTS]);
                }
            }
        }
        g_D[b * NPIX + (tileY * TSY + ty) * WW + (tileX * TSX + tx)] = acc;
    } else {
        // ---- normal table: thread <-> counter gtid; float4 (s0..s3) per iter ----
        uint32_t gtid = (uint32_t)(bi * 256 + tid);   // 0..262143
#pragma unroll
        for (int it = 0; it < 5; it++) {
            float n0 = normal_from_bits(rnd32(keys.k[it][0][0], keys.k[it][0][1], gtid));
            float n1 = normal_from_bits(rnd32(keys.k[it][1][0], keys.k[it][1][1], gtid));
            float n2 = normal_from_bits(rnd32(keys.k[it][2][0], keys.k[it][2][1], gtid));
            float n3 = normal_from_bits(rnd32(keys.k[it][3][0], keys.k[it][3][1], gtid));
            g_N4[(uint32_t)it * 262144u + gtid] = make_float4(n0, n1, n2, n3);
        }
    }
}

// ---------------- kernel 2: init + 5 iterations, halo-split rows ----------------
// One block owns 128 pixels of a row + 5-deep circular halo each side (window
// 138). After iteration k, window pixels [k, 138-k) are bit-correct; after 5
// iterations the 128 owned pixels [5, 133) survive. 2-level speculative random
// search: steps (0,1) and (2,3) each resolved from one parallel 3-load wall —
// selection semantics bit-identical to the sequential chain.
#define WIN 138
#define OWN 128
#define HALO 5
#define MTHREADS 160

__global__ __launch_bounds__(MTHREADS) void kMatch(float* __restrict__ out,
                                                   uint32_t ka, uint32_t kb) {
    __shared__ float sy[2][WIN + 2], sx[2][WIN + 2], sd[2][WIN + 2];
    int bi  = blockIdx.x;                 // 0..1023
    int b   = bi >> 9;                    // batch
    int rem = bi & 511;
    int row = rem >> 1;
    int seg = rem & 1;
    int base = seg * OWN;
    int wp  = threadIdx.x;                // 0..159; active if < WIN
    bool act = wp < WIN;

    int j = (base + wp - HALO) & 255;     // circular column
    int p = (row << 8) | j;

    uint32_t ciy = (uint32_t)(b * 131072 + p);
    uint32_t cix = ciy + 65536u;

    float y = 0.0f, x = 0.0f, d = 0.0f;
    float4 ny4 = make_float4(0.f, 0.f, 0.f, 0.f), nx4 = ny4;
    if (act) {
        y = __fmul_rn(bits_to_f01(rnd32(ka, kb, ciy)), 255.0f);
        x = __fmul_rn(bits_to_f01(rnd32(ka, kb, cix)), 255.0f);
        d = __ldg(&g_D[daddr(b, y, x)]);
        ny4 = __ldg(&g_N4[ciy]);          // iteration 0 normals
        nx4 = __ldg(&g_N4[cix]);
    }

    int tm = max(wp - 1, 0);              // clamped: edges are eroded anyway
    int tp = min(wp + 1, WIN - 1);

#pragma unroll
    for (int it = 0; it < 5; it++) {
        int cb = it & 1;
        if (act) { sy[cb][wp] = y; sx[cb][wp] = x; sd[cb][wp] = d; }

        // prefetch next iteration's normals (hidden under sync + gather walls)
        float4 ny4n = make_float4(0.f, 0.f, 0.f, 0.f), nx4n = ny4n;
        if (act && it < 4) {
            uint32_t nb = (uint32_t)(it + 1) * 262144u;
            ny4n = __ldg(&g_N4[nb + ciy]);
            nx4n = __ldg(&g_N4[nb + cix]);
        }

        __syncthreads();
        float my = sy[cb][tm], mx = sx[cb][tm], md = sd[cb][tm];
        float qy = sy[cb][tp], qx = sx[cb][tp], qd = sd[cb][tp];
        // single sync per iteration: next iteration writes the other buffer

        if (act) {
            // propagate(+1) at j and j+1, then propagate(-1) at j
            float c0y, c0x, c0d, c1y, c1x, c1d;
            if (md < d) { c0y = my; c0x = mx; c0d = md; } else { c0y = y; c0x = x; c0d = d; }
            if (d < qd) { c1y = y;  c1x = x;  c1d = d;  } else { c1y = qy; c1x = qx; c1d = qd; }
            if (c1d < c0d) { y = c1y; x = c1x; d = c1d; } else { y = c0y; x = c0x; d = c0d; }

            // ---- speculative pair (steps 0,1): scales 1.0, 0.5 ----
            {
                float a1y = clipc(__fadd_rn(y, __fmul_rn(ny4.x, 1.0f)));
                float a1x = clipc(__fadd_rn(x, __fmul_rn(nx4.x, 1.0f)));
                float r0y = clipc(__fadd_rn(y,   __fmul_rn(ny4.y, 0.5f)));
                float r0x = clipc(__fadd_rn(x,   __fmul_rn(nx4.y, 0.5f)));
                float r1y = clipc(__fadd_rn(a1y, __fmul_rn(ny4.y, 0.5f)));
                float r1x = clipc(__fadd_rn(a1x, __fmul_rn(nx4.y, 0.5f)));
                float d1  = __ldg(&g_D[daddr(b, a1y, a1x)]);
                float d20 = __ldg(&g_D[daddr(b, r0y, r0x)]);
                float d21 = __ldg(&g_D[daddr(b, r1y, r1x)]);
                bool acc1 = d1 < d;
                if (acc1) { y = a1y; x = a1x; d = d1; }
                float dv = acc1 ? d21 : d20;
                float cy = acc1 ? r1y : r0y;
                float cx = acc1 ? r1x : r0x;
                if (dv < d) { y = cy; x = cx; d = dv; }
            }
            // ---- speculative pair (steps 2,3): scales 0.25, 0.125 ----
            {
                float a1y = clipc(__fadd_rn(y, __fmul_rn(ny4.z, 0.25f)));
                float a1x = clipc(__fadd_rn(x, __fmul_rn(nx4.z, 0.25f)));
                float r0y = clipc(__fadd_rn(y,   __fmul_rn(ny4.w, 0.125f)));
                float r0x = clipc(__fadd_rn(x,   __fmul_rn(nx4.w, 0.125f)));
                float r1y = clipc(__fadd_rn(a1y, __fmul_rn(ny4.w, 0.125f)));
                float r1x = clipc(__fadd_rn(a1x, __fmul_rn(nx4.w, 0.125f)));
                float d1  = __ldg(&g_D[daddr(b, a1y, a1x)]);
                float d20 = __ldg(&g_D[daddr(b, r0y, r0x)]);
                float d21 = __ldg(&g_D[daddr(b, r1y, r1x)]);
                bool acc1 = d1 < d;
                if (acc1) { y = a1y; x = a1x; d = d1; }
                float dv = acc1 ? d21 : d20;
                float cy = acc1 ? r1y : r0y;
                float cx = acc1 ? r1x : r0x;
                if (dv < d) { y = cy; x = cx; d = dv; }
            }
        }
        ny4 = ny4n; nx4 = nx4n;
    }

    if (wp >= HALO && wp < HALO + OWN) {
        out[b * 131072 + p]        = y;
        out[b * 131072 + NPIX + p] = x;
    }
}

// ---------------- host ----------------
extern "C" void kernel_launch(void* const* d_in, const int* in_sizes, int n_in,
                              void* d_out, int out_size) {
    const float* src = (const float*)d_in[0];
    const float* tgt = (const float*)d_in[1];
    float* out = (float*)d_out;
    (void)in_sizes; (void)n_in; (void)out_size;

    uint32_t ki0, ki1, kl0, kl1;
    threefry(0u, 1u, 0u, 0u, ki0, ki1);   // k_init
    threefry(0u, 1u, 0u, 1u, kl0, kl1);   // k_loop

    AllKeys keys;
    for (uint32_t t = 0; t < 5; t++) {
        uint32_t K0, K1;
        threefry(kl0, kl1, 0u, t, K0, K1);        // fold_in(k_loop, t)
        for (int s = 0; s < 4; s++) {
            uint32_t n0, n1, s0, s1;
            threefry(K0, K1, 0u, 0u, n0, n1);     // next key
            threefry(K0, K1, 0u, 1u, s0, s1);     // key for normal draw
            keys.k[t][s][0] = s0;
            keys.k[t][s][1] = s1;
            K0 = n0; K1 = n1;
        }
    }

    kPrep<<<1536, 256>>>(src, tgt, keys);
    kMatch<<<1024, MTHREADS>>>(out, ki0, ki1);
}